// round 1
// baseline (speedup 1.0000x reference)
#include <cuda_runtime.h>
#include <math.h>

// Problem constants
#define CC      50000
#define PP      2048
#define BB      512
#define MCMULT  (4.0f / 2048.0f)
#define EPSV    1e-9f

// Launch geometry
#define BPB     2                      // batches per block
#define NSPLIT  4                      // point splits
#define NP      (PP / NSPLIT)          // 512 points per block
#define NT      (NP / 32)              // 16 tiles of 32 points
#define NBLK    ((BB / BPB) * NSPLIT)  // 1024 blocks -> partials

__device__ double g_partials[NBLK];

__global__ __launch_bounds__(256, 2)
void mb_margin_kernel(const float* __restrict__ cw,
                      const float* __restrict__ pts,
                      const int*   __restrict__ nf1)
{
    // point tile staging: [buf][point][dim], padded to 36 floats/row so
    // LDS.128 (stride 36 words -> 4l+4v+j banks per 8-lane phase) is conflict-free
    __shared__ float  s_pts[2][32][36];
    __shared__ float  s_m[BPB][4][NP];    // raw margins per (batch_sub, box, point)
    __shared__ double s_red[256];

    const int tid  = threadIdx.x;
    const int w    = tid >> 5;
    const int lane = tid & 31;
    const int b0   = blockIdx.x * BPB;
    const int pbase = blockIdx.y * NP;

    // warp -> (batch_sub, box).  box: 0=c/k0 1=c/k1 2=d/k0 3=d/k1
    const int bs  = w >> 2;
    const int box = w & 3;
    const int cls_slot = box >> 1;   // 0 = class c, 1 = class d
    const int k        = box & 1;

    const int cls = nf1[(b0 + bs) * 2 + cls_slot];
    const float* row = cw + (size_t)cls * 128 + (size_t)k * 64;

    // Build mn/mx EXACTLY like the reference: mn = c - |o|, mx = c + |o|
    float mn[32], mx[32];
#pragma unroll
    for (int d0 = 0; d0 < 32; d0 += 4) {
        float4 c4 = *(const float4*)(row + d0);
        float4 o4 = *(const float4*)(row + 32 + d0);
        mn[d0 + 0] = c4.x - fabsf(o4.x);  mx[d0 + 0] = c4.x + fabsf(o4.x);
        mn[d0 + 1] = c4.y - fabsf(o4.y);  mx[d0 + 1] = c4.y + fabsf(o4.y);
        mn[d0 + 2] = c4.z - fabsf(o4.z);  mx[d0 + 2] = c4.z + fabsf(o4.z);
        mn[d0 + 3] = c4.w - fabsf(o4.w);  mx[d0 + 3] = c4.w + fabsf(o4.w);
    }

    // stage tile i into buffer buf (256 threads x 1 float4 = 32 pts x 32 dims)
    auto stage = [&](int i, int buf) {
        const float4* src = (const float4*)(pts + (size_t)(pbase + i * 32) * 32);
        float4 v = src[tid];                       // coalesced 4KB
        int pt = tid >> 3, ch = tid & 7;
        *(float4*)&s_pts[buf][pt][ch * 4] = v;     // 16B aligned (144B rows)
    };

    stage(0, 0);
    for (int i = 0; i < NT; i++) {
        __syncthreads();                 // tile i visible; buf (i+1)&1 free
        if (i + 1 < NT) stage(i + 1, (i + 1) & 1);

        const float* pp = s_pts[i & 1][lane];
        float a0 = 3.0e38f, a1 = 3.0e38f, a2 = 3.0e38f, a3 = 3.0e38f;
#pragma unroll
        for (int c = 0; c < 8; c++) {
            float4 p4 = *(const float4*)(pp + c * 4);
            int d = c * 4;
            a0 = fminf(a0, fminf(p4.x - mn[d + 0], mx[d + 0] - p4.x));
            a1 = fminf(a1, fminf(p4.y - mn[d + 1], mx[d + 1] - p4.y));
            a2 = fminf(a2, fminf(p4.z - mn[d + 2], mx[d + 2] - p4.z));
            a3 = fminf(a3, fminf(p4.w - mn[d + 3], mx[d + 3] - p4.w));
        }
        float m = fminf(fminf(a0, a1), fminf(a2, a3));
        s_m[bs][box][i * 32 + lane] = m;
    }
    __syncthreads();

    // Combine: 2*NP = 1024 (batch_sub, point) pairs, 4 per thread
    double lsum = 0.0;
#pragma unroll
    for (int j = 0; j < (BPB * NP) / 256; j++) {
        int q   = tid + j * 256;
        int bsq = q >> 9;          // NP = 512
        int pl  = q & (NP - 1);
        float mc = fmaxf(s_m[bsq][0][pl], s_m[bsq][1][pl]);
        float md = fmaxf(s_m[bsq][2][pl], s_m[bsq][3][pl]);
        float ci = 1.0f / (1.0f + expf(-mc));   // sigmoid(max) == max(sigmoid)
        float di = 1.0f / (1.0f + expf(-md));
        float inter = (ci + di) * 0.5f;
        float area1 = fmaxf(ci - 0.5f, 0.0f) * MCMULT;
        float iarea = fmaxf(inter - 0.5f, 0.0f) * MCMULT;
        lsum += (double)(iarea / (area1 + EPSV));
    }

    // deterministic block reduction in double
    s_red[tid] = lsum;
    __syncthreads();
#pragma unroll
    for (int s = 128; s > 0; s >>= 1) {
        if (tid < s) s_red[tid] += s_red[tid + s];
        __syncthreads();
    }
    if (tid == 0)
        g_partials[blockIdx.y * gridDim.x + blockIdx.x] = s_red[0];
}

__global__ void mb_final_kernel(float* __restrict__ out)
{
    __shared__ double sr[256];
    double s = 0.0;
    for (int i = threadIdx.x; i < NBLK; i += 256) s += g_partials[i];
    sr[threadIdx.x] = s;
    __syncthreads();
#pragma unroll
    for (int k = 128; k > 0; k >>= 1) {
        if (threadIdx.x < k) sr[threadIdx.x] += sr[threadIdx.x + k];
        __syncthreads();
    }
    if (threadIdx.x == 0) {
        double loss = 1.0 - sr[0] / ((double)BB * (double)PP);
        out[0] = (float)(loss > 0.0 ? loss : 0.0);
    }
}

extern "C" void kernel_launch(void* const* d_in, const int* in_sizes, int n_in,
                              void* d_out, int out_size)
{
    const float* cw   = (const float*)d_in[0];   // class_weight (50000,128)
    const float* pts  = (const float*)d_in[1];   // mc_points    (2048,32)
    const int*   nf1  = (const int*)  d_in[2];   // nf1_data     (512,2)

    dim3 grid(BB / BPB, NSPLIT);
    mb_margin_kernel<<<grid, 256>>>(cw, pts, nf1);
    mb_final_kernel<<<1, 256>>>((float*)d_out);
}

// round 6
// speedup vs baseline: 1.0072x; 1.0072x over previous
#include <cuda_runtime.h>
#include <math.h>

// Problem constants
#define CC      50000
#define PP      2048
#define BB      512
#define MCMULT  (4.0f / 2048.0f)
#define EPSV    1e-9f

// Launch geometry
#define BPB     4                      // batches per block
#define NSPLIT  8                      // point splits
#define NP      (PP / NSPLIT)          // 256 points per block
#define NT      (NP / 32)              // 8 tiles of 32 points
#define NBLK    ((BB / BPB) * NSPLIT)  // 1024 blocks

__device__ double g_partials[NBLK];
__device__ unsigned int g_cnt;         // zero-initialized; reset by last block

__global__ __launch_bounds__(512, 1)
void mb_fused_kernel(const float* __restrict__ cw,
                     const float* __restrict__ pts,
                     const int*   __restrict__ nf1,
                     float*       __restrict__ out)
{
    // [buf][point][dim] padded to 36 words -> LDS.128 phase-conflict-free
    __shared__ float  s_pts[2][32][36];
    __shared__ float  s_m[BPB][4][NP];
    __shared__ double s_warp[16];
    __shared__ int    s_flag;

    const int tid   = threadIdx.x;
    const int w     = tid >> 5;
    const int lane  = tid & 31;
    const int b0    = blockIdx.x * BPB;
    const int pbase = blockIdx.y * NP;

    // warp -> (batch_sub, box). box: 0=c/k0 1=c/k1 2=d/k0 3=d/k1
    const int bs  = w >> 2;
    const int box = w & 3;
    const int cls = nf1[(b0 + bs) * 2 + (box >> 1)];
    const float* row = cw + (size_t)cls * 128 + (size_t)(box & 1) * 64;

    // Box in registers: center cc[], half-width off[] = |o|
    // margin_d = min(p-mn, mx-p) = off_d - |p_d - c_d|   (3 ops/dim)
    float cc[32], off[32];
#pragma unroll
    for (int d = 0; d < 32; d += 4) {
        float4 c4 = *(const float4*)(row + d);
        float4 o4 = *(const float4*)(row + 32 + d);
        cc[d + 0] = c4.x; off[d + 0] = fabsf(o4.x);
        cc[d + 1] = c4.y; off[d + 1] = fabsf(o4.y);
        cc[d + 2] = c4.z; off[d + 2] = fabsf(o4.z);
        cc[d + 3] = c4.w; off[d + 3] = fabsf(o4.w);
    }

    // stage tile i (32 pts x 32 dims = 256 float4) with first 256 threads
    auto stage = [&](int i, int buf) {
        if (tid < 256) {
            const float4* src = (const float4*)(pts + (size_t)(pbase + i * 32) * 32);
            float4 v = src[tid];
            int pt = tid >> 3, ch = tid & 7;
            *(float4*)&s_pts[buf][pt][ch * 4] = v;
        }
    };

    stage(0, 0);
    for (int i = 0; i < NT; i++) {
        __syncthreads();                     // tile i ready; buf (i+1)&1 free
        if (i + 1 < NT) stage(i + 1, (i + 1) & 1);

        const float* pp = s_pts[i & 1][lane];
        float a0 = 3.0e38f, a1 = 3.0e38f, a2 = 3.0e38f, a3 = 3.0e38f;
#pragma unroll
        for (int c = 0; c < 8; c++) {
            float4 p4 = *(const float4*)(pp + c * 4);
            int d = c * 4;
            a0 = fminf(a0, off[d + 0] - fabsf(p4.x - cc[d + 0]));
            a1 = fminf(a1, off[d + 1] - fabsf(p4.y - cc[d + 1]));
            a2 = fminf(a2, off[d + 2] - fabsf(p4.z - cc[d + 2]));
            a3 = fminf(a3, off[d + 3] - fabsf(p4.w - cc[d + 3]));
        }
        s_m[bs][box][i * 32 + lane] = fminf(fminf(a0, a1), fminf(a2, a3));
    }
    __syncthreads();

    // Combine: BPB*NP = 1024 (batch_sub, point) pairs, 2 per thread
    double lsum = 0.0;
#pragma unroll
    for (int j = 0; j < (BPB * NP) / 512; j++) {
        int q   = tid + j * 512;
        int bsq = q >> 8;              // NP = 256
        int pl  = q & (NP - 1);
        float mc = fmaxf(s_m[bsq][0][pl], s_m[bsq][1][pl]);
        float md = fmaxf(s_m[bsq][2][pl], s_m[bsq][3][pl]);
        float ci = 1.0f / (1.0f + __expf(-mc));  // sigmoid(max)==max(sigmoid)
        float di = 1.0f / (1.0f + __expf(-md));
        float inter = (ci + di) * 0.5f;
        float area1 = fmaxf(ci - 0.5f, 0.0f) * MCMULT;
        float iarea = fmaxf(inter - 0.5f, 0.0f) * MCMULT;
        lsum += (double)__fdividef(iarea, area1 + EPSV);
    }

    // warp shfl-reduce -> 16 values -> warp 0 reduces
#pragma unroll
    for (int s = 16; s > 0; s >>= 1)
        lsum += __shfl_down_sync(0xFFFFFFFFu, lsum, s);
    if (lane == 0) s_warp[w] = lsum;
    __syncthreads();

    if (w == 0) {
        double v = (lane < 16) ? s_warp[lane] : 0.0;
#pragma unroll
        for (int s = 8; s > 0; s >>= 1)
            v += __shfl_down_sync(0xFFFFFFFFu, v, s);
        if (lane == 0) {
            int bid = blockIdx.y * gridDim.x + blockIdx.x;
            g_partials[bid] = v;
            __threadfence();
            unsigned old = atomicAdd(&g_cnt, 1u);
            s_flag = (old == NBLK - 1) ? 1 : 0;
        }
    }
    __syncthreads();

    // last block: final reduction of NBLK partials
    if (s_flag) {
        double s = g_partials[tid] + g_partials[tid + 512];
#pragma unroll
        for (int k = 16; k > 0; k >>= 1)
            s += __shfl_down_sync(0xFFFFFFFFu, s, k);
        if (lane == 0) s_warp[w] = s;
        __syncthreads();
        if (w == 0) {
            double v = (lane < 16) ? s_warp[lane] : 0.0;
#pragma unroll
            for (int k = 8; k > 0; k >>= 1)
                v += __shfl_down_sync(0xFFFFFFFFu, v, k);
            if (lane == 0) {
                double loss = 1.0 - v / ((double)BB * (double)PP);
                out[0] = (float)(loss > 0.0 ? loss : 0.0);
                g_cnt = 0u;                 // reset for next graph replay
            }
        }
    }
}

extern "C" void kernel_launch(void* const* d_in, const int* in_sizes, int n_in,
                              void* d_out, int out_size)
{
    const float* cw  = (const float*)d_in[0];   // class_weight (50000,128)
    const float* pts = (const float*)d_in[1];   // mc_points    (2048,32)
    const int*   nf1 = (const int*)  d_in[2];   // nf1_data     (512,2)

    dim3 grid(BB / BPB, NSPLIT);
    mb_fused_kernel<<<grid, 512>>>(cw, pts, nf1, (float*)d_out);
}

// round 9
// speedup vs baseline: 1.8337x; 1.8207x over previous
#include <cuda_runtime.h>
#include <math.h>

// Problem constants
#define CC      50000
#define PP      2048
#define BB      512
#define MCMULT  (4.0f / 2048.0f)
#define EPSV    1e-9f

// Launch geometry: thread = one point; block = 256 points x NB batches
#define PTB     256                    // points per block
#define NB      8                      // batches per block
#define GX      (PP / PTB)             // 8  point splits
#define GY      (BB / NB)              // 64 batch splits
#define NBLK    (GX * GY)              // 512 blocks

__device__ double g_partials[NBLK];
__device__ unsigned int g_cnt;         // zero-init; reset by last block each replay

__global__ __launch_bounds__(256, 3)
void mb_point_kernel(const float* __restrict__ cw,
                     const float* __restrict__ pts,
                     const int*   __restrict__ nf1,
                     float*       __restrict__ out)
{
    __shared__ float  s_pts[PTB][36];      // padded: conflict-free LDS.128 readout
    __shared__ float  s_box[2 * NB][128];  // gathered class rows [c0..c31 o0..o31]x2
    __shared__ int    s_idx[2 * NB];
    __shared__ double s_wsum[8];
    __shared__ int    s_flag;

    const int tid   = threadIdx.x;
    const int w     = tid >> 5;
    const int lane  = tid & 31;
    const int pbase = blockIdx.x * PTB;
    const int b0    = blockIdx.y * NB;

    if (tid < 2 * NB) s_idx[tid] = nf1[b0 * 2 + tid];
    __syncthreads();

    // Stage box rows: 2*NB rows x 128 floats = 512 float4 (coalesced gather)
#pragma unroll
    for (int i = 0; i < (2 * NB * 32) / 256; i++) {
        int f = i * 256 + tid;
        int r = f >> 5, c = f & 31;
        ((float4*)s_box[r])[c] = ((const float4*)(cw + (size_t)s_idx[r] * 128))[c];
    }
    // Stage points: PTB pts x 8 float4 (coalesced), padded rows of 36 words
#pragma unroll
    for (int i = 0; i < (PTB * 8) / 256; i++) {
        int f = i * 256 + tid;
        int pt = f >> 3, ch = f & 7;
        *(float4*)&s_pts[pt][ch * 4] = ((const float4*)pts)[(size_t)pbase * 8 + f];
    }
    __syncthreads();

    // This thread's point -> 32 registers (conflict-free: stride 36 words)
    float p[32];
#pragma unroll
    for (int d = 0; d < 32; d += 4) {
        float4 v = *(const float4*)&s_pts[tid][d];
        p[d + 0] = v.x; p[d + 1] = v.y; p[d + 2] = v.z; p[d + 3] = v.w;
    }

    // Main loop: all reads of box data are warp-uniform LDS broadcasts (N=1)
    float lsum = 0.0f;
#pragma unroll 1
    for (int b = 0; b < NB; b++) {
        float m[4];
#pragma unroll
        for (int box = 0; box < 4; box++) {
            const float* R = &s_box[b * 2 + (box >> 1)][(box & 1) * 64];
            float a0 = 3.0e38f, a1 = 3.0e38f, a2 = 3.0e38f, a3 = 3.0e38f;
#pragma unroll
            for (int j = 0; j < 8; j++) {
                float4 c4 = *(const float4*)(R + j * 4);        // broadcast
                float4 o4 = *(const float4*)(R + 32 + j * 4);   // broadcast
                int d = j * 4;
                // margin_d = |o| - |p - c|   (FADD; FADD |a|,-|b|; FMNMX)
                a0 = fminf(a0, fabsf(o4.x) - fabsf(p[d + 0] - c4.x));
                a1 = fminf(a1, fabsf(o4.y) - fabsf(p[d + 1] - c4.y));
                a2 = fminf(a2, fabsf(o4.z) - fabsf(p[d + 2] - c4.z));
                a3 = fminf(a3, fabsf(o4.w) - fabsf(p[d + 3] - c4.w));
            }
            m[box] = fminf(fminf(a0, a1), fminf(a2, a3));
        }
        float mc = fmaxf(m[0], m[1]);            // sigmoid(max)==max(sigmoid)
        float md = fmaxf(m[2], m[3]);
        float ci = 1.0f / (1.0f + __expf(-mc));
        float di = 1.0f / (1.0f + __expf(-md));
        float inter = (ci + di) * 0.5f;
        float area1 = fmaxf(ci - 0.5f, 0.0f) * MCMULT;
        float iarea = fmaxf(inter - 0.5f, 0.0f) * MCMULT;
        lsum += __fdividef(iarea, area1 + EPSV);
    }

    // Reduce: warp (double) -> block -> grid via last-block-done
    double v = (double)lsum;
#pragma unroll
    for (int s = 16; s > 0; s >>= 1)
        v += __shfl_down_sync(0xFFFFFFFFu, v, s);
    if (lane == 0) s_wsum[w] = v;
    __syncthreads();

    if (w == 0) {
        double t = (lane < 8) ? s_wsum[lane] : 0.0;
#pragma unroll
        for (int s = 4; s > 0; s >>= 1)
            t += __shfl_down_sync(0xFFFFFFFFu, t, s);
        if (lane == 0) {
            int bid = blockIdx.y * gridDim.x + blockIdx.x;
            g_partials[bid] = t;
            __threadfence();
            unsigned old = atomicAdd(&g_cnt, 1u);
            s_flag = (old == NBLK - 1) ? 1 : 0;
        }
    }
    __syncthreads();

    if (s_flag) {   // last block: reduce all 512 partials (2 per thread)
        double s = g_partials[tid] + g_partials[tid + 256];
#pragma unroll
        for (int k = 16; k > 0; k >>= 1)
            s += __shfl_down_sync(0xFFFFFFFFu, s, k);
        if (lane == 0) s_wsum[w] = s;
        __syncthreads();
        if (w == 0) {
            double t = (lane < 8) ? s_wsum[lane] : 0.0;
#pragma unroll
            for (int k = 4; k > 0; k >>= 1)
                t += __shfl_down_sync(0xFFFFFFFFu, t, k);
            if (lane == 0) {
                double loss = 1.0 - t / ((double)BB * (double)PP);
                out[0] = (float)(loss > 0.0 ? loss : 0.0);
                g_cnt = 0u;                     // reset for next graph replay
            }
        }
    }
}

extern "C" void kernel_launch(void* const* d_in, const int* in_sizes, int n_in,
                              void* d_out, int out_size)
{
    const float* cw  = (const float*)d_in[0];   // class_weight (50000,128)
    const float* pts = (const float*)d_in[1];   // mc_points    (2048,32)
    const int*   nf1 = (const int*)  d_in[2];   // nf1_data     (512,2)

    dim3 grid(GX, GY);
    mb_point_kernel<<<grid, PTB>>>(cw, pts, nf1, (float*)d_out);
}

// round 14
// speedup vs baseline: 2.3431x; 1.2778x over previous
#include <cuda_runtime.h>
#include <cuda_bf16.h>
#include <math.h>

// Problem constants
#define PP      2048
#define BB      512
#define MCMULT  (4.0f / 2048.0f)
#define EPSV    1e-9f

// Launch geometry: thread = one point; block = 256 points x NB batches
#define PTB     256
#define NB      8
#define GX      (PP / PTB)             // 8
#define GY      (BB / NB)              // 64
#define NBLK    (GX * GY)              // 512 blocks (single wave at 4/SM)

__device__ double g_partials[NBLK];
__device__ unsigned int g_cnt;         // zero-init; reset by last block each replay

static __device__ __forceinline__ __nv_bfloat162 bcast2(const unsigned int& u) {
    return *reinterpret_cast<const __nv_bfloat162*>(&u);
}

__global__ __launch_bounds__(256, 4)
void mb_bf16_kernel(const float* __restrict__ cw,
                    const float* __restrict__ pts,
                    const int*   __restrict__ nf1,
                    float*       __restrict__ out)
{
    // Point rows: 16 bf16x2 (64B) padded to 20 words (80B): 16B-aligned LDS.128
    // chunks, lane-stride 20 words -> conflict-free 8-lane phases.
    __shared__ unsigned int s_ptsh[PTB][20];
    // Box rows: [mn0..mn15 | mx0..mx15] bf16x2 = 128B per (class,k) box row.
    // 4*NB = 32 rows. Mainloop reads are warp-uniform -> LDS broadcasts.
    __shared__ unsigned int s_box[4 * NB][32];
    __shared__ int    s_idx[2 * NB];
    __shared__ double s_wsum[8];
    __shared__ int    s_flag;

    const int tid   = threadIdx.x;
    const int w     = tid >> 5;
    const int lane  = tid & 31;
    const int pbase = blockIdx.x * PTB;
    const int b0    = blockIdx.y * NB;

    if (tid < 2 * NB) s_idx[tid] = nf1[b0 * 2 + tid];
    __syncthreads();

    // ── Stage boxes: thread -> (box_row r in [0,32), dim-group g in [0,8))
    {
        int r = tid >> 3, g = tid & 7;
        int cls = s_idx[r >> 1];
        int k   = r & 1;
        const float4* base = (const float4*)(cw + (size_t)cls * 128 + (size_t)k * 64);
        float4 c4 = base[g];        // c dims g*4..g*4+3
        float4 o4 = base[8 + g];    // o dims g*4..g*4+3
        float ax = fabsf(o4.x), ay = fabsf(o4.y), az = fabsf(o4.z), aw = fabsf(o4.w);
        __nv_bfloat162 mn0 = __floats2bfloat162_rn(c4.x - ax, c4.y - ay);
        __nv_bfloat162 mn1 = __floats2bfloat162_rn(c4.z - az, c4.w - aw);
        __nv_bfloat162 mx0 = __floats2bfloat162_rn(c4.x + ax, c4.y + ay);
        __nv_bfloat162 mx1 = __floats2bfloat162_rn(c4.z + az, c4.w + aw);
        s_box[r][g * 2 + 0]      = *reinterpret_cast<unsigned int*>(&mn0);
        s_box[r][g * 2 + 1]      = *reinterpret_cast<unsigned int*>(&mn1);
        s_box[r][16 + g * 2 + 0] = *reinterpret_cast<unsigned int*>(&mx0);
        s_box[r][16 + g * 2 + 1] = *reinterpret_cast<unsigned int*>(&mx1);
    }
    // ── Stage points: coalesced f32 loads, convert to bf16x2
#pragma unroll
    for (int i = 0; i < (PTB * 8) / 256; i++) {
        int f = i * 256 + tid;
        int pt = f >> 3, ch = f & 7;
        float4 v = ((const float4*)pts)[(size_t)pbase * 8 + f];
        __nv_bfloat162 h0 = __floats2bfloat162_rn(v.x, v.y);
        __nv_bfloat162 h1 = __floats2bfloat162_rn(v.z, v.w);
        s_ptsh[pt][ch * 2 + 0] = *reinterpret_cast<unsigned int*>(&h0);
        s_ptsh[pt][ch * 2 + 1] = *reinterpret_cast<unsigned int*>(&h1);
    }
    __syncthreads();

    // This thread's point -> 16 bf16x2 registers
    __nv_bfloat162 p2[16];
#pragma unroll
    for (int j = 0; j < 4; j++) {
        uint4 v = *(const uint4*)&s_ptsh[tid][j * 4];
        p2[j * 4 + 0] = bcast2(v.x);
        p2[j * 4 + 1] = bcast2(v.y);
        p2[j * 4 + 2] = bcast2(v.z);
        p2[j * 4 + 3] = bcast2(v.w);
    }

    const __nv_bfloat162 binf = __float2bfloat162_rn(3.0e38f);

    float lsum = 0.0f;
#pragma unroll 1
    for (int b = 0; b < NB; b++) {
        float m[4];
#pragma unroll
        for (int box = 0; box < 4; box++) {
            int r = (2 * b + (box >> 1)) * 2 + (box & 1);
            const unsigned int* BR = s_box[r];
            __nv_bfloat162 a0 = binf, a1 = binf, a2 = binf, a3 = binf;
#pragma unroll
            for (int j = 0; j < 4; j++) {
                uint4 mn4 = *(const uint4*)(BR + j * 4);        // broadcast
                uint4 mx4 = *(const uint4*)(BR + 16 + j * 4);   // broadcast
                int q = j * 4;
                // margin2 = min(p - mn, mx - p), 2 dims per op
                a0 = __hmin2(a0, __hmin2(__hsub2(p2[q + 0], bcast2(mn4.x)),
                                         __hsub2(bcast2(mx4.x), p2[q + 0])));
                a1 = __hmin2(a1, __hmin2(__hsub2(p2[q + 1], bcast2(mn4.y)),
                                         __hsub2(bcast2(mx4.y), p2[q + 1])));
                a2 = __hmin2(a2, __hmin2(__hsub2(p2[q + 2], bcast2(mn4.z)),
                                         __hsub2(bcast2(mx4.z), p2[q + 2])));
                a3 = __hmin2(a3, __hmin2(__hsub2(p2[q + 3], bcast2(mn4.w)),
                                         __hsub2(bcast2(mx4.w), p2[q + 3])));
            }
            a0 = __hmin2(a0, a1);
            a2 = __hmin2(a2, a3);
            a0 = __hmin2(a0, a2);
            m[box] = fminf(__low2float(a0), __high2float(a0));
        }
        float mc = fmaxf(m[0], m[1]);           // sigmoid(max)==max(sigmoid)
        float md = fmaxf(m[2], m[3]);
        float ci = 1.0f / (1.0f + __expf(-mc));
        float di = 1.0f / (1.0f + __expf(-md));
        float inter = (ci + di) * 0.5f;
        float area1 = fmaxf(ci - 0.5f, 0.0f) * MCMULT;
        float iarea = fmaxf(inter - 0.5f, 0.0f) * MCMULT;
        lsum += __fdividef(iarea, area1 + EPSV);
    }

    // Reduce: warp (double) -> block -> grid via last-block-done
    double v = (double)lsum;
#pragma unroll
    for (int s = 16; s > 0; s >>= 1)
        v += __shfl_down_sync(0xFFFFFFFFu, v, s);
    if (lane == 0) s_wsum[w] = v;
    __syncthreads();

    if (w == 0) {
        double t = (lane < 8) ? s_wsum[lane] : 0.0;
#pragma unroll
        for (int s = 4; s > 0; s >>= 1)
            t += __shfl_down_sync(0xFFFFFFFFu, t, s);
        if (lane == 0) {
            int bid = blockIdx.y * gridDim.x + blockIdx.x;
            g_partials[bid] = t;
            __threadfence();
            unsigned old = atomicAdd(&g_cnt, 1u);
            s_flag = (old == NBLK - 1) ? 1 : 0;
        }
    }
    __syncthreads();

    if (s_flag) {   // last block: reduce all 512 partials (2 per thread)
        double s = g_partials[tid] + g_partials[tid + 256];
#pragma unroll
        for (int k = 16; k > 0; k >>= 1)
            s += __shfl_down_sync(0xFFFFFFFFu, s, k);
        if (lane == 0) s_wsum[w] = s;
        __syncthreads();
        if (w == 0) {
            double t = (lane < 8) ? s_wsum[lane] : 0.0;
#pragma unroll
            for (int k = 4; k > 0; k >>= 1)
                t += __shfl_down_sync(0xFFFFFFFFu, t, k);
            if (lane == 0) {
                double loss = 1.0 - t / ((double)BB * (double)PP);
                out[0] = (float)(loss > 0.0 ? loss : 0.0);
                g_cnt = 0u;                     // reset for next graph replay
            }
        }
    }
}

extern "C" void kernel_launch(void* const* d_in, const int* in_sizes, int n_in,
                              void* d_out, int out_size)
{
    const float* cw  = (const float*)d_in[0];   // class_weight (50000,128)
    const float* pts = (const float*)d_in[1];   // mc_points    (2048,32)
    const int*   nf1 = (const int*)  d_in[2];   // nf1_data     (512,2)

    dim3 grid(GX, GY);
    mb_bf16_kernel<<<grid, PTB>>>(cw, pts, nf1, (float*)d_out);
}